// round 14
// baseline (speedup 1.0000x reference)
#include <cuda_runtime.h>
#include <cuda_fp16.h>
#include <cstdint>
#include <cstddef>

// Problem constants
#define BB 4
#define LL 2048
#define DD 1024
#define HH 16
#define HD 64
#define MM (BB * LL)          // 8192
#define D3 (3 * DD)           // 3072

// ---------------------------------------------------------------------------
// Scratch (device globals)
// ---------------------------------------------------------------------------
__device__ __half g_qkvh[(size_t)MM * D3];   // fp16 qkv (hi)
__device__ __half g_qkvl[(size_t)MM * D3];   // fp16 qkv residual (Q cols only)
__device__ __half g_xh[(size_t)MM * DD], g_xl[(size_t)MM * DD];
__device__ __half g_wqh[(size_t)D3 * DD];
__device__ __half g_woh[(size_t)DD * DD];
__device__ __half g_oh[(size_t)MM * DD], g_ol[(size_t)MM * DD];

// ---------------------------------------------------------------------------
// Helpers
// ---------------------------------------------------------------------------
__device__ __forceinline__ uint32_t smem_u32(const void* p) {
    uint32_t a;
    asm("{ .reg .u64 t; cvta.to.shared.u64 t, %1; cvt.u32.u64 %0, t; }"
        : "=r"(a) : "l"(p));
    return a;
}
__device__ __forceinline__ void cp16(uint32_t saddr, const void* gaddr) {
    asm volatile("cp.async.cg.shared.global [%0], [%1], 16;"
                 :: "r"(saddr), "l"(gaddr));
}
__device__ __forceinline__ void cp_commit() {
    asm volatile("cp.async.commit_group;" ::: "memory");
}
template<int N> __device__ __forceinline__ void cp_wait() {
    asm volatile("cp.async.wait_group %0;" :: "n"(N) : "memory");
}
__device__ __forceinline__ void ldsm4(uint32_t& r0, uint32_t& r1, uint32_t& r2,
                                      uint32_t& r3, uint32_t addr) {
    asm volatile("ldmatrix.sync.aligned.m8n8.x4.shared.b16 {%0,%1,%2,%3}, [%4];"
                 : "=r"(r0), "=r"(r1), "=r"(r2), "=r"(r3) : "r"(addr));
}
__device__ __forceinline__ void ldsm4t(uint32_t& r0, uint32_t& r1, uint32_t& r2,
                                       uint32_t& r3, uint32_t addr) {
    asm volatile("ldmatrix.sync.aligned.m8n8.x4.trans.shared.b16 {%0,%1,%2,%3}, [%4];"
                 : "=r"(r0), "=r"(r1), "=r"(r2), "=r"(r3) : "r"(addr));
}
// fp16 HMMA m16n8k16, fp32 accumulate
__device__ __forceinline__ void mma16816h(float* d, const uint32_t* a,
                                          uint32_t b0, uint32_t b1) {
    asm volatile(
        "mma.sync.aligned.m16n8k16.row.col.f32.f16.f16.f32 "
        "{%0,%1,%2,%3}, {%4,%5,%6,%7}, {%8,%9}, {%0,%1,%2,%3};"
        : "+f"(d[0]), "+f"(d[1]), "+f"(d[2]), "+f"(d[3])
        : "r"(a[0]), "r"(a[1]), "r"(a[2]), "r"(a[3]), "r"(b0), "r"(b1));
}
// pack (x,y) to fp16x2 hi, produce fp16x2 lo residual
__device__ __forceinline__ uint32_t packhl(float x, float y, uint32_t& lo) {
    __half2 hv = __floats2half2_rn(x, y);
    float hx = __half2float(__low2half(hv));
    float hy = __half2float(__high2half(hv));
    __half2 lv = __floats2half2_rn(x - hx, y - hy);
    lo = *(uint32_t*)&lv;
    return *(uint32_t*)&hv;
}

// ---------------------------------------------------------------------------
// fp32 -> fp16 hi/lo split (x), fp32 -> fp16 convert (weights)
// ---------------------------------------------------------------------------
__global__ __launch_bounds__(256) void split16_kernel(
    const float* __restrict__ src, __half* __restrict__ hi,
    __half* __restrict__ lo, int n4)
{
    const int i = blockIdx.x * blockDim.x + threadIdx.x;
    if (i >= n4) return;
    float4 v = *(const float4*)(src + (size_t)i * 4);
    uint32_t l0, l1;
    uint32_t h0 = packhl(v.x, v.y, l0);
    uint32_t h1 = packhl(v.z, v.w, l1);
    *(uint2*)(hi + (size_t)i * 4) = make_uint2(h0, h1);
    *(uint2*)(lo + (size_t)i * 4) = make_uint2(l0, l1);
}
__global__ __launch_bounds__(256) void cvt16_kernel(
    const float* __restrict__ src, __half* __restrict__ hi, int n4)
{
    const int i = blockIdx.x * blockDim.x + threadIdx.x;
    if (i >= n4) return;
    float4 v = *(const float4*)(src + (size_t)i * 4);
    __half2 h0 = __floats2half2_rn(v.x, v.y);
    __half2 h1 = __floats2half2_rn(v.z, v.w);
    *(uint2*)(hi + (size_t)i * 4) = make_uint2(*(uint32_t*)&h0, *(uint32_t*)&h1);
}

// ---------------------------------------------------------------------------
// fp16 A2B1 GEMM:  C = (Ah + Al) @ Bh^T    (fp32 acc)
// BM=128, BN=256, BK=32. 8 warps (2m x 4n), warp tile 64x64, 1 CTA/SM.
// 3-stage cp.async pipeline (stage = Ah + Al + Bh = 40960 B).
// MODE 0: fp32 C.  MODE 1: fp16 hi out; lo out + 0.125 scale for cols < 1024.
// ---------------------------------------------------------------------------
#define ROWB 80
#define ATILEB (128 * ROWB)           // 10240
#define BTILEB (256 * ROWB)           // 20480
#define STAGEB (2 * ATILEB + BTILEB)  // 40960: Ah Al Bh
#define GSMEM (3 * STAGEB)            // 122880
#define NCHUNK 32

template<int MODE>
__global__ __launch_bounds__(256, 1) void gemm_f16x2_kernel(
    const __half* __restrict__ Ahi, const __half* __restrict__ Alo,
    const __half* __restrict__ Bhi,
    float* __restrict__ C, __half* __restrict__ Ch, __half* __restrict__ Cl,
    int Nn)
{
    extern __shared__ char smem[];
    const int tid  = threadIdx.x;
    const int lane = tid & 31;
    const int wid  = tid >> 5;
    const int wm   = wid & 1;       // 2 warps in m -> 64 rows each
    const int wn   = wid >> 1;      // 4 warps in n -> 64 cols each
    const int bm   = blockIdx.y * 128;
    const int bn   = blockIdx.x * 256;

    const uint32_t sb = smem_u32(smem);

    // A-load mapping: thread -> row tid>>1, chunks (tid&1)*2, +1
    const int ar = tid >> 1;
    const int ac = (tid & 1) * 2;
    const uint32_t sA0 = (uint32_t)(ar * ROWB + ac * 16);
    const __half* gAh = Ahi + (size_t)(bm + ar) * DD + ac * 8;
    const __half* gAl = Alo + (size_t)(bm + ar) * DD + ac * 8;
    // B-load mapping: thread -> row tid, chunks 0..3
    const uint32_t sB0 = (uint32_t)(tid * ROWB);
    const __half* gB  = Bhi + (size_t)(bn + tid) * DD;

    const uint32_t lm_row = (lane & 15);
    const uint32_t lm_hi  = (lane >> 4) * 16;
    const uint32_t a_base = (wm * 64 + lm_row) * ROWB + lm_hi;
    const uint32_t b_base = (wn * 64 + lm_row) * ROWB + lm_hi;

    float acc[4][8][4];
#pragma unroll
    for (int i = 0; i < 4; i++)
#pragma unroll
        for (int j = 0; j < 8; j++)
#pragma unroll
            for (int k = 0; k < 4; k++) acc[i][j][k] = 0.f;

    auto issue_loads = [&](int kt) {
        const uint32_t st = sb + (uint32_t)(kt % 3) * STAGEB;
        const int ko = kt * 32;
        cp16(st + sA0,                    gAh + ko);
        cp16(st + sA0 + 16,               gAh + ko + 8);
        cp16(st + ATILEB + sA0,           gAl + ko);
        cp16(st + ATILEB + sA0 + 16,      gAl + ko + 8);
#pragma unroll
        for (int c = 0; c < 4; c++)
            cp16(st + 2 * ATILEB + sB0 + c * 16, gB + ko + c * 8);
    };

    issue_loads(0); cp_commit();
    issue_loads(1); cp_commit();

    for (int kt = 0; kt < NCHUNK; kt++) {
        cp_wait<1>();
        __syncthreads();
        if (kt + 2 < NCHUNK) issue_loads(kt + 2);
        cp_commit();

        const uint32_t st = sb + (uint32_t)(kt % 3) * STAGEB;
#pragma unroll
        for (int s = 0; s < 2; s++) {
            const uint32_t sof = s * 32;
            uint32_t bh4[4][4];
#pragma unroll
            for (int i = 0; i < 4; i++)
                ldsm4(bh4[i][0], bh4[i][1], bh4[i][2], bh4[i][3],
                      st + 2 * ATILEB + b_base + i * 16 * ROWB + sof);
            // pass 1: Ah * Bh
            {
                uint32_t ah[4][4];
#pragma unroll
                for (int mf = 0; mf < 4; mf++)
                    ldsm4(ah[mf][0], ah[mf][1], ah[mf][2], ah[mf][3],
                          st + a_base + mf * 16 * ROWB + sof);
#pragma unroll
                for (int mf = 0; mf < 4; mf++)
#pragma unroll
                    for (int nf = 0; nf < 8; nf++) {
                        const int i = nf >> 1, sub = nf & 1;
                        mma16816h(acc[mf][nf], ah[mf],
                                  sub ? bh4[i][1] : bh4[i][0],
                                  sub ? bh4[i][3] : bh4[i][2]);
                    }
            }
            // pass 2: Al * Bh
            {
                uint32_t al4[4][4];
#pragma unroll
                for (int mf = 0; mf < 4; mf++)
                    ldsm4(al4[mf][0], al4[mf][1], al4[mf][2], al4[mf][3],
                          st + ATILEB + a_base + mf * 16 * ROWB + sof);
#pragma unroll
                for (int mf = 0; mf < 4; mf++)
#pragma unroll
                    for (int nf = 0; nf < 8; nf++) {
                        const int i = nf >> 1, sub = nf & 1;
                        mma16816h(acc[mf][nf], al4[mf],
                                  sub ? bh4[i][1] : bh4[i][0],
                                  sub ? bh4[i][3] : bh4[i][2]);
                    }
            }
        }
    }

    // Epilogue
    const int er = lane >> 2;
    const int ec = (lane & 3) * 2;
    const float qs = (MODE == 1 && bn < DD) ? 0.125f : 1.0f;
    const bool wlo = (MODE == 1) && (bn < DD);
#pragma unroll
    for (int mf = 0; mf < 4; mf++) {
        const size_t row0 = (size_t)(bm + wm * 64 + mf * 16 + er) * Nn + bn + wn * 64;
        const size_t row8 = row0 + (size_t)8 * Nn;
#pragma unroll
        for (int nf = 0; nf < 8; nf++) {
            if (MODE == 0) {
                *(float2*)(C + row0 + nf * 8 + ec) = make_float2(acc[mf][nf][0], acc[mf][nf][1]);
                *(float2*)(C + row8 + nf * 8 + ec) = make_float2(acc[mf][nf][2], acc[mf][nf][3]);
            } else {
                uint32_t lo;
                uint32_t hi = packhl(acc[mf][nf][0] * qs, acc[mf][nf][1] * qs, lo);
                *(uint32_t*)(Ch + row0 + nf * 8 + ec) = hi;
                if (wlo) *(uint32_t*)(Cl + row0 + nf * 8 + ec) = lo;
                hi = packhl(acc[mf][nf][2] * qs, acc[mf][nf][3] * qs, lo);
                *(uint32_t*)(Ch + row8 + nf * 8 + ec) = hi;
                if (wlo) *(uint32_t*)(Cl + row8 + nf * 8 + ec) = lo;
            }
        }
    }
}

// ---------------------------------------------------------------------------
// Flash attention, fp16 A2B1: S = (Qh+Ql)Kh^T, O = (Ph+Pl)Vh. fp32 softmax.
// CTA: 128 q-rows, 8 warps x 16 rows. KV tile 64, cp.async double-buffered.
// ---------------------------------------------------------------------------
#define FROWB 144

__global__ __launch_bounds__(256) void flash_f16_kernel(
    const __half* __restrict__ qh_, const __half* __restrict__ ql_,
    __half* __restrict__ oh_, __half* __restrict__ ol_)
{
    __shared__ __align__(16) char fs[2 * 128 * FROWB];   // 36864
    const int bh = blockIdx.y;
    const int b  = bh >> 4;
    const int h  = bh & 15;
    const int qbase = blockIdx.x * 128;
    const int tid = threadIdx.x, lane = tid & 31, w = tid >> 5;
    const uint32_t sb = smem_u32(fs);

    // ---- Load Q hi/lo tile (128 x 64 fp16 each) into smem ----
    const size_t qrow0 = (size_t)b * LL + qbase;
#pragma unroll
    for (int it = 0; it < 8; it++) {
        const int f = it * 256 + tid;                   // 0..2047
        const __half* src = (f & 1024) ? ql_ : qh_;
        const int idx = f & 1023, r = idx >> 3, c = idx & 7;
        uint4 v = *(const uint4*)(src + (qrow0 + r) * D3 + h * HD + c * 8);
        *(uint4*)(fs + ((f >> 10) ? 18432 : 0) + r * FROWB + c * 16) = v;
    }
    __syncthreads();

    // ---- Extract Q A-fragments ----
    uint32_t qfh[4][4], qfl[4][4];
    {
        const uint32_t qa = sb + (uint32_t)((w * 16 + (lane & 15)) * FROWB
                                            + ((lane >> 4) * 16));
#pragma unroll
        for (int kc = 0; kc < 4; kc++) {
            ldsm4(qfh[kc][0], qfh[kc][1], qfh[kc][2], qfh[kc][3], qa + kc * 32);
            ldsm4(qfl[kc][0], qfl[kc][1], qfl[kc][2], qfl[kc][3],
                  qa + 18432 + kc * 32);
        }
    }
    __syncthreads();   // Q smem now reusable as KV buffers

    float o[8][4];
#pragma unroll
    for (int i = 0; i < 8; i++)
#pragma unroll
        for (int j = 0; j < 4; j++) o[i][j] = 0.f;
    float m0 = -1e30f, m1 = -1e30f, l0 = 0.f, l1 = 0.f;
    const int row0 = qbase + w * 16 + (lane >> 2);
    const int ntiles = (qbase >> 6) + 2;

    auto issue_kv = [&](int t) {
        const uint32_t dstb = sb + (uint32_t)(t & 1) * 18432;
#pragma unroll
        for (int it = 0; it < 4; it++) {
            const int f = it * 256 + tid;               // 0..1023
            const int arr = f >> 9, idx = f & 511, r = idx >> 3, c = idx & 7;
            cp16(dstb + arr * 9216 + (uint32_t)(r * FROWB + c * 16),
                 qh_ + ((size_t)b * LL + t * 64 + r) * D3
                     + (arr ? 2 * DD : DD) + h * HD + c * 8);
        }
    };

    issue_kv(0); cp_commit();

    for (int t = 0; t < ntiles; t++) {
        cp_wait<0>();
        __syncthreads();
        if (t + 1 < ntiles) issue_kv(t + 1);
        cp_commit();

        const int kvbase = t * 64;
        if (kvbase > qbase + w * 16 + 15) continue;     // fully masked for warp
        const uint32_t buf = sb + (uint32_t)(t & 1) * 18432;

        // ---- S = (Qh + Ql) Kh^T ----
        float s[8][4];
#pragma unroll
        for (int i = 0; i < 8; i++)
#pragma unroll
            for (int j = 0; j < 4; j++) s[i][j] = 0.f;
#pragma unroll
        for (int nt2 = 0; nt2 < 4; nt2++) {
#pragma unroll
            for (int kc = 0; kc < 4; kc++) {
                uint32_t kh4[4];
                const uint32_t ka = buf + (uint32_t)((nt2 * 16 + (lane & 15)) * FROWB
                                    + ((lane >> 4) * 16) + kc * 32);
                ldsm4(kh4[0], kh4[1], kh4[2], kh4[3], ka);
                mma16816h(s[2 * nt2],     qfh[kc], kh4[0], kh4[2]);
                mma16816h(s[2 * nt2],     qfl[kc], kh4[0], kh4[2]);
                mma16816h(s[2 * nt2 + 1], qfh[kc], kh4[1], kh4[3]);
                mma16816h(s[2 * nt2 + 1], qfl[kc], kh4[1], kh4[3]);
            }
        }

        // ---- Causal mask ----
        if (kvbase + 63 > qbase + w * 16) {
#pragma unroll
            for (int t8 = 0; t8 < 8; t8++) {
                const int c0 = kvbase + t8 * 8 + (lane & 3) * 2;
                if (c0 > row0)         s[t8][0] = -1e30f;
                if (c0 + 1 > row0)     s[t8][1] = -1e30f;
                if (c0 > row0 + 8)     s[t8][2] = -1e30f;
                if (c0 + 1 > row0 + 8) s[t8][3] = -1e30f;
            }
        }

        // ---- Online softmax ----
        float tm0 = -1e30f, tm1 = -1e30f;
#pragma unroll
        for (int t8 = 0; t8 < 8; t8++) {
            tm0 = fmaxf(tm0, fmaxf(s[t8][0], s[t8][1]));
            tm1 = fmaxf(tm1, fmaxf(s[t8][2], s[t8][3]));
        }
        tm0 = fmaxf(tm0, __shfl_xor_sync(0xFFFFFFFFu, tm0, 1));
        tm0 = fmaxf(tm0, __shfl_xor_sync(0xFFFFFFFFu, tm0, 2));
        tm1 = fmaxf(tm1, __shfl_xor_sync(0xFFFFFFFFu, tm1, 1));
        tm1 = fmaxf(tm1, __shfl_xor_sync(0xFFFFFFFFu, tm1, 2));
        const float mn0 = fmaxf(m0, tm0), mn1 = fmaxf(m1, tm1);
        const float a0 = __expf(m0 - mn0), a1 = __expf(m1 - mn1);
        m0 = mn0; m1 = mn1;
        float rs0 = 0.f, rs1 = 0.f;
#pragma unroll
        for (int t8 = 0; t8 < 8; t8++) {
            s[t8][0] = __expf(s[t8][0] - m0);
            s[t8][1] = __expf(s[t8][1] - m0);
            s[t8][2] = __expf(s[t8][2] - m1);
            s[t8][3] = __expf(s[t8][3] - m1);
            rs0 += s[t8][0] + s[t8][1];
            rs1 += s[t8][2] + s[t8][3];
        }
        l0 = l0 * a0 + rs0;
        l1 = l1 * a1 + rs1;
#pragma unroll
        for (int dt = 0; dt < 8; dt++) {
            o[dt][0] *= a0; o[dt][1] *= a0;
            o[dt][2] *= a1; o[dt][3] *= a1;
        }

        // ---- P -> fp16 hi/lo A-fragments ----
        uint32_t ph[4][4], pl[4][4];
#pragma unroll
        for (int kc = 0; kc < 4; kc++) {
            ph[kc][0] = packhl(s[2 * kc][0],     s[2 * kc][1],     pl[kc][0]);
            ph[kc][1] = packhl(s[2 * kc][2],     s[2 * kc][3],     pl[kc][1]);
            ph[kc][2] = packhl(s[2 * kc + 1][0], s[2 * kc + 1][1], pl[kc][2]);
            ph[kc][3] = packhl(s[2 * kc + 1][2], s[2 * kc + 1][3], pl[kc][3]);
        }

        // ---- O += (Ph + Pl) Vh ----
#pragma unroll
        for (int dt2 = 0; dt2 < 4; dt2++) {
#pragma unroll
            for (int kc = 0; kc < 4; kc++) {
                uint32_t vh4[4];
                const uint32_t va = buf + 9216
                    + (uint32_t)((kc * 16 + ((lane >> 3) & 1) * 8 + (lane & 7)) * FROWB
                                 + (dt2 * 16 + (lane >> 4) * 8) * 2);
                ldsm4t(vh4[0], vh4[1], vh4[2], vh4[3], va);
                mma16816h(o[2 * dt2],     ph[kc], vh4[0], vh4[1]);
                mma16816h(o[2 * dt2 + 1], ph[kc], vh4[2], vh4[3]);
                mma16816h(o[2 * dt2],     pl[kc], vh4[0], vh4[1]);
                mma16816h(o[2 * dt2 + 1], pl[kc], vh4[2], vh4[3]);
            }
        }
    }

    // ---- Finalize ----
    l0 += __shfl_xor_sync(0xFFFFFFFFu, l0, 1);
    l0 += __shfl_xor_sync(0xFFFFFFFFu, l0, 2);
    l1 += __shfl_xor_sync(0xFFFFFFFFu, l1, 1);
    l1 += __shfl_xor_sync(0xFFFFFFFFu, l1, 2);
    const float inv0 = 1.f / l0, inv1 = 1.f / l1;
    const size_t gr0 = (size_t)b * LL + qbase + w * 16 + (lane >> 2);
    const int gc0 = h * HD + (lane & 3) * 2;
#pragma unroll
    for (int t8 = 0; t8 < 8; t8++) {
        uint32_t lo;
        uint32_t hi = packhl(o[t8][0] * inv0, o[t8][1] * inv0, lo);
        *(uint32_t*)(oh_ + gr0 * DD + gc0 + t8 * 8) = hi;
        *(uint32_t*)(ol_ + gr0 * DD + gc0 + t8 * 8) = lo;
        hi = packhl(o[t8][2] * inv1, o[t8][3] * inv1, lo);
        *(uint32_t*)(oh_ + (gr0 + 8) * DD + gc0 + t8 * 8) = hi;
        *(uint32_t*)(ol_ + (gr0 + 8) * DD + gc0 + t8 * 8) = lo;
    }
}

// ---------------------------------------------------------------------------
// Launch
// ---------------------------------------------------------------------------
extern "C" void kernel_launch(void* const* d_in, const int* in_sizes, int n_in,
                              void* d_out, int out_size)
{
    const float* x    = (const float*)d_in[0];
    const float* Wqkv = (const float*)d_in[1];
    const float* Wout = (const float*)d_in[2];
    if (n_in >= 3 && in_sizes[1] == DD * DD && in_sizes[2] == 3 * DD * DD) {
        const float* t = Wqkv; Wqkv = Wout; Wout = t;
    }
    float* out = (float*)d_out;

    __half *qkvh, *qkvl, *xh, *xl, *wqh, *woh, *oh, *ol;
    cudaGetSymbolAddress((void**)&qkvh, g_qkvh);
    cudaGetSymbolAddress((void**)&qkvl, g_qkvl);
    cudaGetSymbolAddress((void**)&xh, g_xh);
    cudaGetSymbolAddress((void**)&xl, g_xl);
    cudaGetSymbolAddress((void**)&wqh, g_wqh);
    cudaGetSymbolAddress((void**)&woh, g_woh);
    cudaGetSymbolAddress((void**)&oh, g_oh);
    cudaGetSymbolAddress((void**)&ol, g_ol);

    cudaFuncSetAttribute(gemm_f16x2_kernel<0>,
                         cudaFuncAttributeMaxDynamicSharedMemorySize, GSMEM);
    cudaFuncSetAttribute(gemm_f16x2_kernel<1>,
                         cudaFuncAttributeMaxDynamicSharedMemorySize, GSMEM);

    // x -> fp16 hi/lo split; weights -> single fp16
    split16_kernel<<<(MM * DD / 4 + 255) / 256, 256>>>(x, xh, xl, MM * DD / 4);
    cvt16_kernel<<<(D3 * DD / 4 + 255) / 256, 256>>>(Wqkv, wqh, D3 * DD / 4);
    cvt16_kernel<<<(DD * DD / 4 + 255) / 256, 256>>>(Wout, woh, DD * DD / 4);

    // 1) QKV projection -> fp16 qkv (hi; lo for Q cols), Q pre-scaled 0.125
    gemm_f16x2_kernel<1><<<dim3(D3 / 256, MM / 128), 256, GSMEM>>>(
        xh, xl, wqh, nullptr, qkvh, qkvl, D3);

    // 2) Causal flash attention -> fp16 hi/lo O
    flash_f16_kernel<<<dim3(LL / 128, BB * HH), 256>>>(qkvh, qkvl, oh, ol);

    // 3) Output projection -> fp32 d_out
    gemm_f16x2_kernel<0><<<dim3(DD / 256, MM / 128), 256, GSMEM>>>(
        oh, ol, woh, out, nullptr, nullptr, DD);
}

// round 16
// speedup vs baseline: 1.1884x; 1.1884x over previous
#include <cuda_runtime.h>
#include <cuda_fp16.h>
#include <cstdint>
#include <cstddef>

// Problem constants
#define BB 4
#define LL 2048
#define DD 1024
#define HH 16
#define HD 64
#define MM (BB * LL)          // 8192
#define D3 (3 * DD)           // 3072

// ---------------------------------------------------------------------------
// Scratch (device globals)
// ---------------------------------------------------------------------------
__device__ __half g_qkvh[(size_t)MM * D3];   // fp16 qkv (hi)
__device__ __half g_qkvl[(size_t)MM * D3];   // fp16 qkv residual (Q cols only)
__device__ __half g_xh[(size_t)MM * DD], g_xl[(size_t)MM * DD];
__device__ __half g_wqh[(size_t)D3 * DD];
__device__ __half g_woh[(size_t)DD * DD];
__device__ __half g_oh[(size_t)MM * DD], g_ol[(size_t)MM * DD];

// ---------------------------------------------------------------------------
// Helpers
// ---------------------------------------------------------------------------
__device__ __forceinline__ uint32_t smem_u32(const void* p) {
    uint32_t a;
    asm("{ .reg .u64 t; cvta.to.shared.u64 t, %1; cvt.u32.u64 %0, t; }"
        : "=r"(a) : "l"(p));
    return a;
}
__device__ __forceinline__ void cp16(uint32_t saddr, const void* gaddr) {
    asm volatile("cp.async.cg.shared.global [%0], [%1], 16;"
                 :: "r"(saddr), "l"(gaddr));
}
__device__ __forceinline__ void cp_commit() {
    asm volatile("cp.async.commit_group;" ::: "memory");
}
template<int N> __device__ __forceinline__ void cp_wait() {
    asm volatile("cp.async.wait_group %0;" :: "n"(N) : "memory");
}
__device__ __forceinline__ void ldsm4(uint32_t& r0, uint32_t& r1, uint32_t& r2,
                                      uint32_t& r3, uint32_t addr) {
    asm volatile("ldmatrix.sync.aligned.m8n8.x4.shared.b16 {%0,%1,%2,%3}, [%4];"
                 : "=r"(r0), "=r"(r1), "=r"(r2), "=r"(r3) : "r"(addr));
}
__device__ __forceinline__ void ldsm4t(uint32_t& r0, uint32_t& r1, uint32_t& r2,
                                       uint32_t& r3, uint32_t addr) {
    asm volatile("ldmatrix.sync.aligned.m8n8.x4.trans.shared.b16 {%0,%1,%2,%3}, [%4];"
                 : "=r"(r0), "=r"(r1), "=r"(r2), "=r"(r3) : "r"(addr));
}
// fp16 HMMA m16n8k16, fp32 accumulate
__device__ __forceinline__ void mma16816h(float* d, const uint32_t* a,
                                          uint32_t b0, uint32_t b1) {
    asm volatile(
        "mma.sync.aligned.m16n8k16.row.col.f32.f16.f16.f32 "
        "{%0,%1,%2,%3}, {%4,%5,%6,%7}, {%8,%9}, {%0,%1,%2,%3};"
        : "+f"(d[0]), "+f"(d[1]), "+f"(d[2]), "+f"(d[3])
        : "r"(a[0]), "r"(a[1]), "r"(a[2]), "r"(a[3]), "r"(b0), "r"(b1));
}
// pack (x,y) to fp16x2 hi, produce fp16x2 lo residual
__device__ __forceinline__ uint32_t packhl(float x, float y, uint32_t& lo) {
    __half2 hv = __floats2half2_rn(x, y);
    float hx = __half2float(__low2half(hv));
    float hy = __half2float(__high2half(hv));
    __half2 lv = __floats2half2_rn(x - hx, y - hy);
    lo = *(uint32_t*)&lv;
    return *(uint32_t*)&hv;
}

// ---------------------------------------------------------------------------
// fp32 -> fp16 hi/lo split (x), fp32 -> fp16 convert (weights)
// ---------------------------------------------------------------------------
__global__ __launch_bounds__(256) void split16_kernel(
    const float* __restrict__ src, __half* __restrict__ hi,
    __half* __restrict__ lo, int n4)
{
    const int i = blockIdx.x * blockDim.x + threadIdx.x;
    if (i >= n4) return;
    float4 v = *(const float4*)(src + (size_t)i * 4);
    uint32_t l0, l1;
    uint32_t h0 = packhl(v.x, v.y, l0);
    uint32_t h1 = packhl(v.z, v.w, l1);
    *(uint2*)(hi + (size_t)i * 4) = make_uint2(h0, h1);
    *(uint2*)(lo + (size_t)i * 4) = make_uint2(l0, l1);
}
__global__ __launch_bounds__(256) void cvt16_kernel(
    const float* __restrict__ src, __half* __restrict__ hi, int n4)
{
    const int i = blockIdx.x * blockDim.x + threadIdx.x;
    if (i >= n4) return;
    float4 v = *(const float4*)(src + (size_t)i * 4);
    __half2 h0 = __floats2half2_rn(v.x, v.y);
    __half2 h1 = __floats2half2_rn(v.z, v.w);
    *(uint2*)(hi + (size_t)i * 4) = make_uint2(*(uint32_t*)&h0, *(uint32_t*)&h1);
}

// ---------------------------------------------------------------------------
// fp16 A2B1 GEMM:  C = (Ah + Al) @ Bh^T    (fp32 acc)
// BM=BN=128, BK=32, 8 warps (2m x 4n), warp 64x32, 2 CTA/SM, 3-stage cp.async.
// MODE 0: fp32 C out.
// MODE 1: fp16 hi out; lo out + 0.125 scale for cols < 1024 (Q).
//         For cols >= 1024 (K,V): the Al correction pass is SKIPPED — those
//         outputs are rounded to fp16 on store anyway, so the correction is
//         dominated by the store rounding.
// ---------------------------------------------------------------------------
#define ROWB 80
#define TILEB (128 * ROWB)            // 10240
#define STAGEB (3 * TILEB)            // 30720: Ah Al Bh
#define GSMEM (3 * STAGEB)            // 92160
#define NCHUNK 32

template<int MODE>
__global__ __launch_bounds__(256, 2) void gemm_f16x2_kernel(
    const __half* __restrict__ Ahi, const __half* __restrict__ Alo,
    const __half* __restrict__ Bhi,
    float* __restrict__ C, __half* __restrict__ Ch, __half* __restrict__ Cl,
    int Nn)
{
    extern __shared__ char smem[];
    const int tid  = threadIdx.x;
    const int lane = tid & 31;
    const int wid  = tid >> 5;
    const int wm   = wid & 1;
    const int wn   = wid >> 1;
    const int bm   = blockIdx.y * 128;
    const int bn   = blockIdx.x * 128;

    // Q columns (bn < DD) need the Al correction pass; K/V columns skip it.
    const bool doAl = (MODE == 0) || (bn < DD);

    const uint32_t sb = smem_u32(smem);

    const int f0 = tid * 2;
    const int r0_ = f0 >> 2, c0_ = f0 & 3;
    const int r1_ = (f0 + 1) >> 2, c1_ = (f0 + 1) & 3;
    const uint32_t s0 = (uint32_t)(r0_ * ROWB + c0_ * 16);
    const uint32_t s1 = (uint32_t)(r1_ * ROWB + c1_ * 16);

    const __half* gA0h = Ahi + (size_t)(bm + r0_) * DD + c0_ * 8;
    const __half* gA1h = Ahi + (size_t)(bm + r1_) * DD + c1_ * 8;
    const __half* gA0l = Alo + (size_t)(bm + r0_) * DD + c0_ * 8;
    const __half* gA1l = Alo + (size_t)(bm + r1_) * DD + c1_ * 8;
    const __half* gB0h = Bhi + (size_t)(bn + r0_) * DD + c0_ * 8;
    const __half* gB1h = Bhi + (size_t)(bn + r1_) * DD + c1_ * 8;

    const uint32_t lm_row = (lane & 15);
    const uint32_t lm_hi  = (lane >> 4) * 16;
    const uint32_t a_base = (wm * 64 + lm_row) * ROWB + lm_hi;
    const uint32_t b_base = (wn * 32 + lm_row) * ROWB + lm_hi;

    float acc[4][4][4];
#pragma unroll
    for (int i = 0; i < 4; i++)
#pragma unroll
        for (int j = 0; j < 4; j++)
#pragma unroll
            for (int k = 0; k < 4; k++) acc[i][j][k] = 0.f;

    auto issue_loads = [&](int kt) {
        const uint32_t st = sb + (uint32_t)(kt % 3) * STAGEB;
        const int ko = kt * 32;
        cp16(st + s0,             gA0h + ko);
        cp16(st + s1,             gA1h + ko);
        if (doAl) {
            cp16(st + TILEB + s0, gA0l + ko);
            cp16(st + TILEB + s1, gA1l + ko);
        }
        cp16(st + 2 * TILEB + s0, gB0h + ko);
        cp16(st + 2 * TILEB + s1, gB1h + ko);
    };

    issue_loads(0); cp_commit();
    issue_loads(1); cp_commit();

    for (int kt = 0; kt < NCHUNK; kt++) {
        cp_wait<1>();
        __syncthreads();
        if (kt + 2 < NCHUNK) issue_loads(kt + 2);
        cp_commit();

        const uint32_t st = sb + (uint32_t)(kt % 3) * STAGEB;
#pragma unroll
        for (int s = 0; s < 2; s++) {
            const uint32_t sof = s * 32;
            uint32_t ah[4][4], bh2[2][4];
#pragma unroll
            for (int mf = 0; mf < 4; mf++)
                ldsm4(ah[mf][0], ah[mf][1], ah[mf][2], ah[mf][3],
                      st + a_base + mf * 16 * ROWB + sof);
#pragma unroll
            for (int i = 0; i < 2; i++)
                ldsm4(bh2[i][0], bh2[i][1], bh2[i][2], bh2[i][3],
                      st + 2 * TILEB + b_base + i * 16 * ROWB + sof);
            // pass 1: Ah * Bh
#pragma unroll
            for (int mf = 0; mf < 4; mf++)
#pragma unroll
                for (int nf = 0; nf < 4; nf++) {
                    const int i = nf >> 1, sub = nf & 1;
                    mma16816h(acc[mf][nf], ah[mf],
                              sub ? bh2[i][1] : bh2[i][0],
                              sub ? bh2[i][3] : bh2[i][2]);
                }
            // pass 2: Al * Bh  (skipped for K/V column tiles in MODE 1)
            if (doAl) {
                uint32_t al4[4][4];
#pragma unroll
                for (int mf = 0; mf < 4; mf++)
                    ldsm4(al4[mf][0], al4[mf][1], al4[mf][2], al4[mf][3],
                          st + TILEB + a_base + mf * 16 * ROWB + sof);
#pragma unroll
                for (int mf = 0; mf < 4; mf++)
#pragma unroll
                    for (int nf = 0; nf < 4; nf++) {
                        const int i = nf >> 1, sub = nf & 1;
                        mma16816h(acc[mf][nf], al4[mf],
                                  sub ? bh2[i][1] : bh2[i][0],
                                  sub ? bh2[i][3] : bh2[i][2]);
                    }
            }
        }
    }

    // Epilogue
    const int er = lane >> 2;
    const int ec = (lane & 3) * 2;
    const float qs = (MODE == 1 && bn < DD) ? 0.125f : 1.0f;
    const bool wlo = (MODE == 1) && (bn < DD);
#pragma unroll
    for (int mf = 0; mf < 4; mf++) {
        const size_t row0 = (size_t)(bm + wm * 64 + mf * 16 + er) * Nn + bn + wn * 32;
        const size_t row8 = row0 + (size_t)8 * Nn;
#pragma unroll
        for (int nf = 0; nf < 4; nf++) {
            if (MODE == 0) {
                *(float2*)(C + row0 + nf * 8 + ec) = make_float2(acc[mf][nf][0], acc[mf][nf][1]);
                *(float2*)(C + row8 + nf * 8 + ec) = make_float2(acc[mf][nf][2], acc[mf][nf][3]);
            } else {
                uint32_t lo;
                uint32_t hi = packhl(acc[mf][nf][0] * qs, acc[mf][nf][1] * qs, lo);
                *(uint32_t*)(Ch + row0 + nf * 8 + ec) = hi;
                if (wlo) *(uint32_t*)(Cl + row0 + nf * 8 + ec) = lo;
                hi = packhl(acc[mf][nf][2] * qs, acc[mf][nf][3] * qs, lo);
                *(uint32_t*)(Ch + row8 + nf * 8 + ec) = hi;
                if (wlo) *(uint32_t*)(Cl + row8 + nf * 8 + ec) = lo;
            }
        }
    }
}

// ---------------------------------------------------------------------------
// Flash attention, fp16 A2B1: S = (Qh+Ql)Kh^T, O = (Ph+Pl)Vh. fp32 softmax.
// CTA: 128 q-rows, 8 warps x 16 rows. KV tile 64, cp.async double-buffered.
// ---------------------------------------------------------------------------
#define FROWB 144

__global__ __launch_bounds__(256) void flash_f16_kernel(
    const __half* __restrict__ qh_, const __half* __restrict__ ql_,
    __half* __restrict__ oh_, __half* __restrict__ ol_)
{
    __shared__ __align__(16) char fs[2 * 128 * FROWB];   // 36864
    const int bh = blockIdx.y;
    const int b  = bh >> 4;
    const int h  = bh & 15;
    const int qbase = blockIdx.x * 128;
    const int tid = threadIdx.x, lane = tid & 31, w = tid >> 5;
    const uint32_t sb = smem_u32(fs);

    // ---- Load Q hi/lo tile (128 x 64 fp16 each) into smem ----
    const size_t qrow0 = (size_t)b * LL + qbase;
#pragma unroll
    for (int it = 0; it < 8; it++) {
        const int f = it * 256 + tid;                   // 0..2047
        const __half* src = (f & 1024) ? ql_ : qh_;
        const int idx = f & 1023, r = idx >> 3, c = idx & 7;
        uint4 v = *(const uint4*)(src + (qrow0 + r) * D3 + h * HD + c * 8);
        *(uint4*)(fs + ((f >> 10) ? 18432 : 0) + r * FROWB + c * 16) = v;
    }
    __syncthreads();

    // ---- Extract Q A-fragments ----
    uint32_t qfh[4][4], qfl[4][4];
    {
        const uint32_t qa = sb + (uint32_t)((w * 16 + (lane & 15)) * FROWB
                                            + ((lane >> 4) * 16));
#pragma unroll
        for (int kc = 0; kc < 4; kc++) {
            ldsm4(qfh[kc][0], qfh[kc][1], qfh[kc][2], qfh[kc][3], qa + kc * 32);
            ldsm4(qfl[kc][0], qfl[kc][1], qfl[kc][2], qfl[kc][3],
                  qa + 18432 + kc * 32);
        }
    }
    __syncthreads();   // Q smem now reusable as KV buffers

    float o[8][4];
#pragma unroll
    for (int i = 0; i < 8; i++)
#pragma unroll
        for (int j = 0; j < 4; j++) o[i][j] = 0.f;
    float m0 = -1e30f, m1 = -1e30f, l0 = 0.f, l1 = 0.f;
    const int row0 = qbase + w * 16 + (lane >> 2);
    const int ntiles = (qbase >> 6) + 2;

    auto issue_kv = [&](int t) {
        const uint32_t dstb = sb + (uint32_t)(t & 1) * 18432;
#pragma unroll
        for (int it = 0; it < 4; it++) {
            const int f = it * 256 + tid;               // 0..1023
            const int arr = f >> 9, idx = f & 511, r = idx >> 3, c = idx & 7;
            cp16(dstb + arr * 9216 + (uint32_t)(r * FROWB + c * 16),
                 qh_ + ((size_t)b * LL + t * 64 + r) * D3
                     + (arr ? 2 * DD : DD) + h * HD + c * 8);
        }
    };

    issue_kv(0); cp_commit();

    for (int t = 0; t < ntiles; t++) {
        cp_wait<0>();
        __syncthreads();
        if (t + 1 < ntiles) issue_kv(t + 1);
        cp_commit();

        const int kvbase = t * 64;
        if (kvbase > qbase + w * 16 + 15) continue;     // fully masked for warp
        const uint32_t buf = sb + (uint32_t)(t & 1) * 18432;

        // ---- S = (Qh + Ql) Kh^T ----
        float s[8][4];
#pragma unroll
        for (int i = 0; i < 8; i++)
#pragma unroll
            for (int j = 0; j < 4; j++) s[i][j] = 0.f;
#pragma unroll
        for (int nt2 = 0; nt2 < 4; nt2++) {
#pragma unroll
            for (int kc = 0; kc < 4; kc++) {
                uint32_t kh4[4];
                const uint32_t ka = buf + (uint32_t)((nt2 * 16 + (lane & 15)) * FROWB
                                    + ((lane >> 4) * 16) + kc * 32);
                ldsm4(kh4[0], kh4[1], kh4[2], kh4[3], ka);
                mma16816h(s[2 * nt2],     qfh[kc], kh4[0], kh4[2]);
                mma16816h(s[2 * nt2],     qfl[kc], kh4[0], kh4[2]);
                mma16816h(s[2 * nt2 + 1], qfh[kc], kh4[1], kh4[3]);
                mma16816h(s[2 * nt2 + 1], qfl[kc], kh4[1], kh4[3]);
            }
        }

        // ---- Causal mask ----
        if (kvbase + 63 > qbase + w * 16) {
#pragma unroll
            for (int t8 = 0; t8 < 8; t8++) {
                const int c0 = kvbase + t8 * 8 + (lane & 3) * 2;
                if (c0 > row0)         s[t8][0] = -1e30f;
                if (c0 + 1 > row0)     s[t8][1] = -1e30f;
                if (c0 > row0 + 8)     s[t8][2] = -1e30f;
                if (c0 + 1 > row0 + 8) s[t8][3] = -1e30f;
            }
        }

        // ---- Online softmax ----
        float tm0 = -1e30f, tm1 = -1e30f;
#pragma unroll
        for (int t8 = 0; t8 < 8; t8++) {
            tm0 = fmaxf(tm0, fmaxf(s[t8][0], s[t8][1]));
            tm1 = fmaxf(tm1, fmaxf(s[t8][2], s[t8][3]));
        }
        tm0 = fmaxf(tm0, __shfl_xor_sync(0xFFFFFFFFu, tm0, 1));
        tm0 = fmaxf(tm0, __shfl_xor_sync(0xFFFFFFFFu, tm0, 2));
        tm1 = fmaxf(tm1, __shfl_xor_sync(0xFFFFFFFFu, tm1, 1));
        tm1 = fmaxf(tm1, __shfl_xor_sync(0xFFFFFFFFu, tm1, 2));
        const float mn0 = fmaxf(m0, tm0), mn1 = fmaxf(m1, tm1);
        const float a0 = __expf(m0 - mn0), a1 = __expf(m1 - mn1);
        m0 = mn0; m1 = mn1;
        float rs0 = 0.f, rs1 = 0.f;
#pragma unroll
        for (int t8 = 0; t8 < 8; t8++) {
            s[t8][0] = __expf(s[t8][0] - m0);
            s[t8][1] = __expf(s[t8][1] - m0);
            s[t8][2] = __expf(s[t8][2] - m1);
            s[t8][3] = __expf(s[t8][3] - m1);
            rs0 += s[t8][0] + s[t8][1];
            rs1 += s[t8][2] + s[t8][3];
        }
        l0 = l0 * a0 + rs0;
        l1 = l1 * a1 + rs1;
#pragma unroll
        for (int dt = 0; dt < 8; dt++) {
            o[dt][0] *= a0; o[dt][1] *= a0;
            o[dt][2] *= a1; o[dt][3] *= a1;
        }

        // ---- P -> fp16 hi/lo A-fragments ----
        uint32_t ph[4][4], pl[4][4];
#pragma unroll
        for (int kc = 0; kc < 4; kc++) {
            ph[kc][0] = packhl(s[2 * kc][0],     s[2 * kc][1],     pl[kc][0]);
            ph[kc][1] = packhl(s[2 * kc][2],     s[2 * kc][3],     pl[kc][1]);
            ph[kc][2] = packhl(s[2 * kc + 1][0], s[2 * kc + 1][1], pl[kc][2]);
            ph[kc][3] = packhl(s[2 * kc + 1][2], s[2 * kc + 1][3], pl[kc][3]);
        }

        // ---- O += (Ph + Pl) Vh ----
#pragma unroll
        for (int dt2 = 0; dt2 < 4; dt2++) {
#pragma unroll
            for (int kc = 0; kc < 4; kc++) {
                uint32_t vh4[4];
                const uint32_t va = buf + 9216
                    + (uint32_t)((kc * 16 + ((lane >> 3) & 1) * 8 + (lane & 7)) * FROWB
                                 + (dt2 * 16 + (lane >> 4) * 8) * 2);
                ldsm4t(vh4[0], vh4[1], vh4[2], vh4[3], va);
                mma16816h(o[2 * dt2],     ph[kc], vh4[0], vh4[1]);
                mma16816h(o[2 * dt2 + 1], ph[kc], vh4[2], vh4[3]);
                mma16816h(o[2 * dt2],     pl[kc], vh4[0], vh4[1]);
                mma16816h(o[2 * dt2 + 1], pl[kc], vh4[2], vh4[3]);
            }
        }
    }

    // ---- Finalize ----
    l0 += __shfl_xor_sync(0xFFFFFFFFu, l0, 1);
    l0 += __shfl_xor_sync(0xFFFFFFFFu, l0, 2);
    l1 += __shfl_xor_sync(0xFFFFFFFFu, l1, 1);
    l1 += __shfl_xor_sync(0xFFFFFFFFu, l1, 2);
    const float inv0 = 1.f / l0, inv1 = 1.f / l1;
    const size_t gr0 = (size_t)b * LL + qbase + w * 16 + (lane >> 2);
    const int gc0 = h * HD + (lane & 3) * 2;
#pragma unroll
    for (int t8 = 0; t8 < 8; t8++) {
        uint32_t lo;
        uint32_t hi = packhl(o[t8][0] * inv0, o[t8][1] * inv0, lo);
        *(uint32_t*)(oh_ + gr0 * DD + gc0 + t8 * 8) = hi;
        *(uint32_t*)(ol_ + gr0 * DD + gc0 + t8 * 8) = lo;
        hi = packhl(o[t8][2] * inv1, o[t8][3] * inv1, lo);
        *(uint32_t*)(oh_ + (gr0 + 8) * DD + gc0 + t8 * 8) = hi;
        *(uint32_t*)(ol_ + (gr0 + 8) * DD + gc0 + t8 * 8) = lo;
    }
}

// ---------------------------------------------------------------------------
// Launch
// ---------------------------------------------------------------------------
extern "C" void kernel_launch(void* const* d_in, const int* in_sizes, int n_in,
                              void* d_out, int out_size)
{
    const float* x    = (const float*)d_in[0];
    const float* Wqkv = (const float*)d_in[1];
    const float* Wout = (const float*)d_in[2];
    if (n_in >= 3 && in_sizes[1] == DD * DD && in_sizes[2] == 3 * DD * DD) {
        const float* t = Wqkv; Wqkv = Wout; Wout = t;
    }
    float* out = (float*)d_out;

    __half *qkvh, *qkvl, *xh, *xl, *wqh, *woh, *oh, *ol;
    cudaGetSymbolAddress((void**)&qkvh, g_qkvh);
    cudaGetSymbolAddress((void**)&qkvl, g_qkvl);
    cudaGetSymbolAddress((void**)&xh, g_xh);
    cudaGetSymbolAddress((void**)&xl, g_xl);
    cudaGetSymbolAddress((void**)&wqh, g_wqh);
    cudaGetSymbolAddress((void**)&woh, g_woh);
    cudaGetSymbolAddress((void**)&oh, g_oh);
    cudaGetSymbolAddress((void**)&ol, g_ol);

    cudaFuncSetAttribute(gemm_f16x2_kernel<0>,
                         cudaFuncAttributeMaxDynamicSharedMemorySize, GSMEM);
    cudaFuncSetAttribute(gemm_f16x2_kernel<1>,
                         cudaFuncAttributeMaxDynamicSharedMemorySize, GSMEM);

    // x -> fp16 hi/lo split; weights -> single fp16
    split16_kernel<<<(MM * DD / 4 + 255) / 256, 256>>>(x, xh, xl, MM * DD / 4);
    cvt16_kernel<<<(D3 * DD / 4 + 255) / 256, 256>>>(Wqkv, wqh, D3 * DD / 4);
    cvt16_kernel<<<(DD * DD / 4 + 255) / 256, 256>>>(Wout, woh, DD * DD / 4);

    // 1) QKV projection -> fp16 qkv (hi; lo for Q cols), Q pre-scaled 0.125
    gemm_f16x2_kernel<1><<<dim3(D3 / 128, MM / 128), 256, GSMEM>>>(
        xh, xl, wqh, nullptr, qkvh, qkvl, D3);

    // 2) Causal flash attention -> fp16 hi/lo O
    flash_f16_kernel<<<dim3(LL / 128, BB * HH), 256>>>(qkvh, qkvl, oh, ol);

    // 3) Output projection -> fp32 d_out
    gemm_f16x2_kernel<0><<<dim3(DD / 128, MM / 128), 256, GSMEM>>>(
        oh, ol, woh, out, nullptr, nullptr, DD);
}